// round 14
// baseline (speedup 1.0000x reference)
#include <cuda_runtime.h>
#include <cuda_fp16.h>
#include <cstdint>

// Problem constants: B=2, T=2048, C=1024, H=16, D=64
#define BB   2
#define TT   2048
#define CC   1024
#define NH   16
#define HD   64
#define MROWS (BB*TT)          // 4096

// Scratch buffers (no cudaMalloc allowed)
__device__ __half g_qkvh[(size_t)MROWS * 3 * CC];    // [B*T, 3C] half (GEMM1 out)
__device__ __half g_atth[(size_t)MROWS * CC];        // attention out, half
__device__ __half g_xh[(size_t)MROWS * CC];          // x, half
__device__ __half g_wqkvT[(size_t)3 * CC * CC];      // w_qkv^T [3C][C], half
__device__ __half g_woutT[(size_t)CC * CC];          // w_out^T [C][C], half

// ---------------------------------------------------------------------------
// helpers
// ---------------------------------------------------------------------------
__device__ __forceinline__ uint32_t smem_u32(const void* p) {
    uint32_t a;
    asm("{ .reg .u64 t; cvta.to.shared.u64 t, %1; cvt.u32.u64 %0, t; }" : "=r"(a) : "l"(p));
    return a;
}
__device__ __forceinline__ void cpa16(uint32_t dst, const void* src) {
    asm volatile("cp.async.cg.shared.global [%0], [%1], 16;" :: "r"(dst), "l"(src));
}
#define CPA_COMMIT()  asm volatile("cp.async.commit_group;" ::: "memory")
#define CPA_WAIT(n)   asm volatile("cp.async.wait_group %0;" :: "n"(n) : "memory")

__device__ __forceinline__ unsigned packh2(float a, float b) {
    __half2 h = __float22half2_rn(make_float2(a, b));
    return *(unsigned*)&h;
}

// fp16 mma: D(16x8,f32) += A(16x16,f16) @ B(16x8,f16)
__device__ __forceinline__ void mma16(float4& d,
    unsigned a0, unsigned a1, unsigned a2, unsigned a3,
    unsigned b0, unsigned b1)
{
    asm volatile(
        "mma.sync.aligned.m16n8k16.row.col.f32.f16.f16.f32 "
        "{%0,%1,%2,%3}, {%4,%5,%6,%7}, {%8,%9}, {%0,%1,%2,%3};\n"
        : "+f"(d.x), "+f"(d.y), "+f"(d.z), "+f"(d.w)
        : "r"(a0), "r"(a1), "r"(a2), "r"(a3), "r"(b0), "r"(b1));
}

// ldmatrix x4 (b16), non-transposed
__device__ __forceinline__ void ldmx4(unsigned& r0, unsigned& r1,
                                      unsigned& r2, unsigned& r3, uint32_t addr)
{
    asm volatile(
        "ldmatrix.sync.aligned.m8n8.x4.shared.b16 {%0,%1,%2,%3}, [%4];"
        : "=r"(r0), "=r"(r1), "=r"(r2), "=r"(r3) : "r"(addr));
}
// ldmatrix x4 (b16), transposed
__device__ __forceinline__ void ldmx4t(unsigned& r0, unsigned& r1,
                                       unsigned& r2, unsigned& r3, uint32_t addr)
{
    asm volatile(
        "ldmatrix.sync.aligned.m8n8.x4.trans.shared.b16 {%0,%1,%2,%3}, [%4];"
        : "=r"(r0), "=r"(r1), "=r"(r2), "=r"(r3) : "r"(addr));
}

// epilogue store helpers (fp32 accum -> OT pair)
__device__ __forceinline__ void store2(float* C, size_t off, float a, float b) {
    *(float2*)(C + off) = make_float2(a, b);
}
__device__ __forceinline__ void store2(__half* C, size_t off, float a, float b) {
    *(__half2*)(C + off) = __float22half2_rn(make_float2(a, b));
}

// ---------------------------------------------------------------------------
// prepass kernels
// ---------------------------------------------------------------------------
__global__ void cvt_h(const float* __restrict__ in, __half* __restrict__ out, int n4)
{
    int i = blockIdx.x * blockDim.x + threadIdx.x;
    if (i < n4) {
        float4 v = ((const float4*)in)[i];
        ((__half2*)out)[2 * i]     = __float22half2_rn(make_float2(v.x, v.y));
        ((__half2*)out)[2 * i + 1] = __float22half2_rn(make_float2(v.z, v.w));
    }
}

__global__ void transpose_h(const float* __restrict__ in, __half* __restrict__ out,
                            int R, int Cn)
{
    __shared__ float t[32][33];
    int bx = blockIdx.x * 32, by = blockIdx.y * 32;
    int tx = threadIdx.x, ty = threadIdx.y;
    #pragma unroll
    for (int j = 0; j < 32; j += 8)
        t[ty + j][tx] = in[(size_t)(by + ty + j) * Cn + bx + tx];
    __syncthreads();
    #pragma unroll
    for (int j = 0; j < 32; j += 8)
        out[(size_t)(bx + ty + j) * R + by + tx] = __float2half_rn(t[tx][ty + j]);
}

// ---------------------------------------------------------------------------
// fp16 GEMM: C[M,N] = A[M,K] @ Bt[N,K]^T + bias[N]
// 128x128 CTA, BK=64, 128 thr (4 warps 2m x 2n), WARP TILE 64x64.
// 3-stage cp.async, ONE barrier per 64-K chunk.
// Per ks-step per warp: 8 ldmatrix.x4 feed 32 mma16 (ratio 4.0).
// Stage: A 128x72 + B 128x72 halves; row stride 144 B (conflict-free).
// ---------------------------------------------------------------------------
template<typename OT>
__global__ __launch_bounds__(128) void gemm_h(
    const __half* __restrict__ A, const __half* __restrict__ Bt,
    const float* __restrict__ bias, OT* __restrict__ C,
    int M, int N, int K)
{
    extern __shared__ uint32_t smu[];
    const int STG = 9216;                 // u32 per stage (A 4608 + B 4608)
    const uint32_t sbase = smem_u32(smu);

    const int tid  = threadIdx.x;
    const int lane = tid & 31, warp = tid >> 5;
    const int wm = warp & 1;              // 64-row half
    const int wn = warp >> 1;             // 64-col half
    const int qp = lane & 3, qr = lane >> 2;
    const int brow = blockIdx.y * 128;
    const int bcol = blockIdx.x * 128;

    // ldmatrix lane-address components (row stride 144 B)
    const int lx15 = lane & 15;
    const int lhi  = lane >> 4;
    const int l8   = (lane >> 3) & 1;
    const int lx7  = lane & 7;
    const uint32_t aoff = (uint32_t)(wm * 64 + lx15) * 144 + lhi * 16;
    const uint32_t boff = 4608u * 4 + (uint32_t)(wn * 64 + lhi * 8 + lx7) * 144 + l8 * 16;

    float4 acc[4][8];
    #pragma unroll
    for (int i = 0; i < 4; ++i)
        #pragma unroll
        for (int j = 0; j < 8; ++j) acc[i][j] = make_float4(0.f, 0.f, 0.f, 0.f);

    const int NCH = K >> 6;               // 64-half K chunks

    // load roles: 1024 16B-chunks per tensor per stage; 128 thr x 8 iters
    auto load_stage = [&](int kt) {
        uint32_t base = sbase + (kt % 3) * STG * 4;
        #pragma unroll
        for (int i = 0; i < 8; ++i) {
            int idx = i * 128 + tid;       // 0..1023
            int row = idx >> 3;            // 0..127
            int c8  = idx & 7;             // 0..7 (8 halves each)
            uint32_t soff = (uint32_t)row * 144 + c8 * 16;
            cpa16(base + soff,
                  A + (size_t)(brow + row) * K + kt * 64 + c8 * 8);
            cpa16(base + 4608 * 4 + soff,
                  Bt + (size_t)(bcol + row) * K + kt * 64 + c8 * 8);
        }
        CPA_COMMIT();
    };

    load_stage(0);
    load_stage(1);

    for (int kt = 0; kt < NCH; ++kt) {
        if (kt + 1 < NCH) { CPA_WAIT(1); } else { CPA_WAIT(0); }
        __syncthreads();
        // prefetch into stage (kt+2)%3 == (kt-1)%3 — all warps done reading it
        if (kt + 2 < NCH) load_stage(kt + 2);

        const uint32_t base = sbase + (kt % 3) * STG * 4;
        #pragma unroll
        for (int ks = 0; ks < 4; ++ks) {
            unsigned af[4][4];
            #pragma unroll
            for (int mt = 0; mt < 4; ++mt)
                ldmx4(af[mt][0], af[mt][1], af[mt][2], af[mt][3],
                      base + aoff + (uint32_t)mt * (16 * 144) + ks * 32);
            unsigned bf[8][2];
            #pragma unroll
            for (int ntp = 0; ntp < 4; ++ntp)
                ldmx4(bf[2*ntp][0], bf[2*ntp][1], bf[2*ntp+1][0], bf[2*ntp+1][1],
                      base + boff + (uint32_t)ntp * (16 * 144) + ks * 32);
            #pragma unroll
            for (int mt = 0; mt < 4; ++mt)
                #pragma unroll
                for (int nt = 0; nt < 8; ++nt)
                    mma16(acc[mt][nt], af[mt][0], af[mt][1], af[mt][2], af[mt][3],
                          bf[nt][0], bf[nt][1]);
        }
    }

    #pragma unroll
    for (int mt = 0; mt < 4; ++mt) {
        int r0 = brow + wm * 64 + mt * 16 + qr;
        #pragma unroll
        for (int nt = 0; nt < 8; ++nt) {
            int c = bcol + wn * 64 + nt * 8 + 2 * qp;
            float bx = bias[c], by = bias[c + 1];
            store2(C, (size_t)r0       * N + c, acc[mt][nt].x + bx, acc[mt][nt].y + by);
            store2(C, (size_t)(r0 + 8) * N + c, acc[mt][nt].z + bx, acc[mt][nt].w + by);
        }
    }
}

// ---------------------------------------------------------------------------
// Flash attention, fp16 m16n8k16, zero-shuffle P reuse. (unchanged from R13)
// cp.async DOUBLE-BUFFERED K/V (one barrier/tile), ldmatrix for K and V frags.
// CTA: 64 q-rows (4 warps x 16), k-tiles of 64. qkv is HALF.
// Dynamic smem: 2 buffers x (K 64x72 + V 64x72) halves = 36864 B.
// ---------------------------------------------------------------------------
__global__ __launch_bounds__(128) void attn_h(
    const __half* __restrict__ qkv, __half* __restrict__ out)
{
    extern __shared__ __half smh[];
    const uint32_t sb = smem_u32(smh);
    const uint32_t KBUFB = 18432;      // bytes per (K+V) buffer
    const uint32_t VOFF  = 9216;       // V offset within buffer

    const int tid  = threadIdx.x;
    const int lane = tid & 31, w = tid >> 5;
    const int h = blockIdx.y, b = blockIdx.z;
    const int q0 = blockIdx.x * 64;
    const int qp = lane & 3;
    const int qr = lane >> 2;
    const unsigned FULL = 0xffffffffu;

    // ldmatrix lane components (row stride 144 B)
    const int lx7 = lane & 7;
    const int lhi = lane >> 4;
    const int l8  = (lane >> 3) & 1;
    const uint32_t kfoff = (uint32_t)(lhi * 8 + lx7) * 144 + l8 * 16;   // K frags (non-trans)
    const int lrow = lane & 15;                                          // V frags (trans)
    const int lcol = (lane >> 4) * 8;

    // ---- Q fragments (half2 loads, scale 0.125 exact in half) ----
    unsigned qa[4][4];
    {
        const __half2 sc2 = __half2half2(__float2half(0.125f));
        const __half* Qg = qkv + (size_t)(b*TT + q0 + w*16) * (3*CC) + h*HD;
        #pragma unroll
        for (int ks = 0; ks < 4; ++ks) {
            int c0 = ks * 16 + 2 * qp;
            __half2 v00 = __hmul2(*(const __half2*)(Qg + (size_t)qr     * (3*CC) + c0), sc2);
            __half2 v10 = __hmul2(*(const __half2*)(Qg + (size_t)(qr+8) * (3*CC) + c0), sc2);
            __half2 v01 = __hmul2(*(const __half2*)(Qg + (size_t)qr     * (3*CC) + c0 + 8), sc2);
            __half2 v11 = __hmul2(*(const __half2*)(Qg + (size_t)(qr+8) * (3*CC) + c0 + 8), sc2);
            qa[ks][0] = *(unsigned*)&v00;
            qa[ks][1] = *(unsigned*)&v10;
            qa[ks][2] = *(unsigned*)&v01;
            qa[ks][3] = *(unsigned*)&v11;
        }
    }

    float4 o[8];
    #pragma unroll
    for (int i = 0; i < 8; ++i) o[i] = make_float4(0.f, 0.f, 0.f, 0.f);
    float m0 = -1e30f, m1 = -1e30f, l0 = 0.f, l1 = 0.f;

    const int nd = q0 >> 6;            // last key-tile index

    // K/V tile load: 64 keys x 64 halves each = 512 16B-chunks per tensor
    auto loadkv = [&](int kt, int buf) {
        const __half* kb = qkv + (size_t)(b*TT + kt*64) * (3*CC) + CC + h*HD;
        const __half* vb = kb + CC;
        const uint32_t kbuf = sb + buf * KBUFB;
        #pragma unroll
        for (int i = 0; i < 4; ++i) {
            int idx = i * 128 + tid;       // 0..511
            int key = idx >> 3;            // 0..63
            int d8  = (idx & 7) * 8;       // 0..56
            uint32_t off = (key * 72 + d8) * 2;
            const size_t g = (size_t)key * (3*CC) + d8;
            cpa16(kbuf + off,        kb + g);
            cpa16(kbuf + VOFF + off, vb + g);
        }
        CPA_COMMIT();
    };

    loadkv(0, 0);
    for (int kt = 0; kt <= nd; ++kt) {
        CPA_WAIT(0);
        __syncthreads();
        if (kt < nd) loadkv(kt + 1, (kt + 1) & 1);

        const uint32_t kbuf = sb + (kt & 1) * KBUFB;
        const uint32_t vbuf = kbuf + VOFF;

        // ---- S = Q @ K^T  (16 x 64), K frags via ldmatrix.x4 ----
        float4 s[8];
        #pragma unroll
        for (int nt = 0; nt < 8; ++nt) s[nt] = make_float4(0.f, 0.f, 0.f, 0.f);
        #pragma unroll
        for (int ks = 0; ks < 4; ++ks) {
            #pragma unroll
            for (int ntp = 0; ntp < 4; ++ntp) {
                unsigned b00, b01, b10, b11;
                ldmx4(b00, b01, b10, b11,
                      kbuf + kfoff + (uint32_t)ntp * (16 * 144) + ks * 32);
                mma16(s[2*ntp],     qa[ks][0], qa[ks][1], qa[ks][2], qa[ks][3], b00, b01);
                mma16(s[2*ntp + 1], qa[ks][0], qa[ks][1], qa[ks][2], qa[ks][3], b10, b11);
            }
        }

        // ---- causal mask (diagonal tile only) ----
        if (kt == nd) {
            const int rg0 = q0 + w * 16 + qr;
            const int rg1 = rg0 + 8;
            #pragma unroll
            for (int nt = 0; nt < 8; ++nt) {
                int cg = kt * 64 + nt * 8 + 2 * qp;
                if (cg     > rg0) s[nt].x = -1e30f;
                if (cg + 1 > rg0) s[nt].y = -1e30f;
                if (cg     > rg1) s[nt].z = -1e30f;
                if (cg + 1 > rg1) s[nt].w = -1e30f;
            }
        }

        // ---- online softmax ----
        float mx0 = -1e30f, mx1 = -1e30f;
        #pragma unroll
        for (int nt = 0; nt < 8; ++nt) {
            mx0 = fmaxf(mx0, fmaxf(s[nt].x, s[nt].y));
            mx1 = fmaxf(mx1, fmaxf(s[nt].z, s[nt].w));
        }
        mx0 = fmaxf(mx0, __shfl_xor_sync(FULL, mx0, 1));
        mx0 = fmaxf(mx0, __shfl_xor_sync(FULL, mx0, 2));
        mx1 = fmaxf(mx1, __shfl_xor_sync(FULL, mx1, 1));
        mx1 = fmaxf(mx1, __shfl_xor_sync(FULL, mx1, 2));

        float nm0 = fmaxf(m0, mx0), nm1 = fmaxf(m1, mx1);
        float al0 = __expf(m0 - nm0), al1 = __expf(m1 - nm1);
        m0 = nm0; m1 = nm1;

        float sum0 = 0.f, sum1 = 0.f;
        #pragma unroll
        for (int nt = 0; nt < 8; ++nt) {
            s[nt].x = __expf(s[nt].x - m0);
            s[nt].y = __expf(s[nt].y - m0);
            s[nt].z = __expf(s[nt].z - m1);
            s[nt].w = __expf(s[nt].w - m1);
            sum0 += s[nt].x + s[nt].y;
            sum1 += s[nt].z + s[nt].w;
        }
        sum0 += __shfl_xor_sync(FULL, sum0, 1);
        sum0 += __shfl_xor_sync(FULL, sum0, 2);
        sum1 += __shfl_xor_sync(FULL, sum1, 1);
        sum1 += __shfl_xor_sync(FULL, sum1, 2);
        l0 = l0 * al0 + sum0;
        l1 = l1 * al1 + sum1;
        #pragma unroll
        for (int nt = 0; nt < 8; ++nt) {
            o[nt].x *= al0; o[nt].y *= al0; o[nt].z *= al1; o[nt].w *= al1;
        }

        // ---- O += P @ V : S packs into A-frags; V B-frags via ldmatrix.trans ----
        #pragma unroll
        for (int j = 0; j < 4; ++j) {
            unsigned a0 = packh2(s[2*j].x,     s[2*j].y);
            unsigned a1 = packh2(s[2*j].z,     s[2*j].w);
            unsigned a2 = packh2(s[2*j + 1].x, s[2*j + 1].y);
            unsigned a3 = packh2(s[2*j + 1].z, s[2*j + 1].w);
            const int kb = j * 16;            // key group
            const uint32_t rowaddr = vbuf + ((kb + lrow) * 72 + lcol) * 2;
            #pragma unroll
            for (int g2 = 0; g2 < 4; ++g2) {  // d-pair groups (nt = 2g2, 2g2+1)
                unsigned b00, b01, b10, b11;
                ldmx4t(b00, b01, b10, b11, rowaddr + g2 * 32);
                mma16(o[2*g2],     a0, a1, a2, a3, b00, b01);
                mma16(o[2*g2 + 1], a0, a1, a2, a3, b10, b11);
            }
        }
    }

    // ---- writeout to HALF [B*T, C] ----
    const float inv0 = 1.f / l0, inv1 = 1.f / l1;
    const int rg0 = b * TT + q0 + w * 16 + qr;
    __half* ob = out + (size_t)rg0 * CC + h * HD;
    #pragma unroll
    for (int nt = 0; nt < 8; ++nt) {
        int c = nt * 8 + 2 * qp;
        *(__half2*)(ob + c) =
            __float22half2_rn(make_float2(o[nt].x * inv0, o[nt].y * inv0));
        *(__half2*)(ob + (size_t)8 * CC + c) =
            __float22half2_rn(make_float2(o[nt].z * inv1, o[nt].w * inv1));
    }
}

// ---------------------------------------------------------------------------
extern "C" void kernel_launch(void* const* d_in, const int* in_sizes, int n_in,
                              void* d_out, int out_size)
{
    (void)in_sizes; (void)n_in; (void)out_size;
    const float* x     = (const float*)d_in[0];
    const float* w_qkv = (const float*)d_in[1];
    const float* b_qkv = (const float*)d_in[2];
    const float* w_out = (const float*)d_in[3];
    const float* b_out = (const float*)d_in[4];
    float* out = (float*)d_out;

    __half *qkvh, *atth, *xh, *wqkvT, *woutT;
    cudaGetSymbolAddress((void**)&qkvh,  g_qkvh);
    cudaGetSymbolAddress((void**)&atth,  g_atth);
    cudaGetSymbolAddress((void**)&xh,    g_xh);
    cudaGetSymbolAddress((void**)&wqkvT, g_wqkvT);
    cudaGetSymbolAddress((void**)&woutT, g_woutT);

    const int GEMM_SMEM = 3 * 9216 * 4;   // 110592 B
    const int ATTN_SMEM = 2 * 18432;      // 36864 B
    cudaFuncSetAttribute(gemm_h<__half>, cudaFuncAttributeMaxDynamicSharedMemorySize, GEMM_SMEM);
    cudaFuncSetAttribute(gemm_h<float>,  cudaFuncAttributeMaxDynamicSharedMemorySize, GEMM_SMEM);

    // 0) prepass: x -> half; weights -> transposed half [N][K]
    cvt_h<<<(MROWS * CC / 4 + 255) / 256, 256>>>(x, xh, MROWS * CC / 4);
    {
        dim3 blk(32, 8);
        transpose_h<<<dim3(3 * CC / 32, CC / 32), blk>>>(w_qkv, wqkvT, CC, 3 * CC);
        transpose_h<<<dim3(CC / 32, CC / 32), blk>>>(w_out, woutT, CC, CC);
    }

    // 1) qkv = x @ w_qkv + b_qkv   (M=4096, N=3072, K=1024) -> HALF
    {
        dim3 grid(3 * CC / 128, MROWS / 128);
        gemm_h<__half><<<grid, 128, GEMM_SMEM>>>(xh, wqkvT, b_qkv, qkvh, MROWS, 3 * CC, CC);
    }
    // 2) fused causal attention -> atth (half) [B*T, C]
    {
        dim3 grid(TT / 64, NH, BB);
        attn_h<<<grid, 128, ATTN_SMEM>>>(qkvh, atth);
    }
    // 3) out = att @ w_out + b_out (M=4096, N=1024, K=1024) -> fp32
    {
        dim3 grid(CC / 128, MROWS / 128);
        gemm_h<float><<<grid, 128, GEMM_SMEM>>>(atth, woutT, b_out, out, MROWS, CC, CC);
    }
}

// round 15
// speedup vs baseline: 1.0260x; 1.0260x over previous
#include <cuda_runtime.h>
#include <cuda_fp16.h>
#include <cstdint>

// Problem constants: B=2, T=2048, C=1024, H=16, D=64
#define BB   2
#define TT   2048
#define CC   1024
#define NH   16
#define HD   64
#define MROWS (BB*TT)          // 4096

// Scratch buffers (no cudaMalloc allowed)
__device__ __half g_qkvh[(size_t)MROWS * 3 * CC];    // [B*T, 3C] half (GEMM1 out)
__device__ __half g_atth[(size_t)MROWS * CC];        // attention out, half
__device__ __half g_xh[(size_t)MROWS * CC];          // x, half
__device__ __half g_wqkvT[(size_t)3 * CC * CC];      // w_qkv^T [3C][C], half
__device__ __half g_woutT[(size_t)CC * CC];          // w_out^T [C][C], half

// ---------------------------------------------------------------------------
// helpers
// ---------------------------------------------------------------------------
__device__ __forceinline__ uint32_t smem_u32(const void* p) {
    uint32_t a;
    asm("{ .reg .u64 t; cvta.to.shared.u64 t, %1; cvt.u32.u64 %0, t; }" : "=r"(a) : "l"(p));
    return a;
}
__device__ __forceinline__ void cpa16(uint32_t dst, const void* src) {
    asm volatile("cp.async.cg.shared.global [%0], [%1], 16;" :: "r"(dst), "l"(src));
}
#define CPA_COMMIT()  asm volatile("cp.async.commit_group;" ::: "memory")
#define CPA_WAIT(n)   asm volatile("cp.async.wait_group %0;" :: "n"(n) : "memory")

__device__ __forceinline__ unsigned packh2(float a, float b) {
    __half2 h = __float22half2_rn(make_float2(a, b));
    return *(unsigned*)&h;
}
__device__ __forceinline__ float fexp2(float x) {
    float r; asm("ex2.approx.f32 %0, %1;" : "=f"(r) : "f"(x)); return r;
}

// fp16 mma: D(16x8,f32) += A(16x16,f16) @ B(16x8,f16)
__device__ __forceinline__ void mma16(float4& d,
    unsigned a0, unsigned a1, unsigned a2, unsigned a3,
    unsigned b0, unsigned b1)
{
    asm volatile(
        "mma.sync.aligned.m16n8k16.row.col.f32.f16.f16.f32 "
        "{%0,%1,%2,%3}, {%4,%5,%6,%7}, {%8,%9}, {%0,%1,%2,%3};\n"
        : "+f"(d.x), "+f"(d.y), "+f"(d.z), "+f"(d.w)
        : "r"(a0), "r"(a1), "r"(a2), "r"(a3), "r"(b0), "r"(b1));
}

// ldmatrix x4 (b16), non-transposed
__device__ __forceinline__ void ldmx4(unsigned& r0, unsigned& r1,
                                      unsigned& r2, unsigned& r3, uint32_t addr)
{
    asm volatile(
        "ldmatrix.sync.aligned.m8n8.x4.shared.b16 {%0,%1,%2,%3}, [%4];"
        : "=r"(r0), "=r"(r1), "=r"(r2), "=r"(r3) : "r"(addr));
}
// ldmatrix x4 (b16), transposed
__device__ __forceinline__ void ldmx4t(unsigned& r0, unsigned& r1,
                                       unsigned& r2, unsigned& r3, uint32_t addr)
{
    asm volatile(
        "ldmatrix.sync.aligned.m8n8.x4.trans.shared.b16 {%0,%1,%2,%3}, [%4];"
        : "=r"(r0), "=r"(r1), "=r"(r2), "=r"(r3) : "r"(addr));
}

// epilogue store helpers (fp32 accum -> OT pair)
__device__ __forceinline__ void store2(float* C, size_t off, float a, float b) {
    *(float2*)(C + off) = make_float2(a, b);
}
__device__ __forceinline__ void store2(__half* C, size_t off, float a, float b) {
    *(__half2*)(C + off) = __float22half2_rn(make_float2(a, b));
}

// ---------------------------------------------------------------------------
// prepass kernels
// ---------------------------------------------------------------------------
__global__ void cvt_h(const float* __restrict__ in, __half* __restrict__ out, int n4)
{
    int i = blockIdx.x * blockDim.x + threadIdx.x;
    if (i < n4) {
        float4 v = ((const float4*)in)[i];
        ((__half2*)out)[2 * i]     = __float22half2_rn(make_float2(v.x, v.y));
        ((__half2*)out)[2 * i + 1] = __float22half2_rn(make_float2(v.z, v.w));
    }
}

__global__ void transpose_h(const float* __restrict__ in, __half* __restrict__ out,
                            int R, int Cn)
{
    __shared__ float t[32][33];
    int bx = blockIdx.x * 32, by = blockIdx.y * 32;
    int tx = threadIdx.x, ty = threadIdx.y;
    #pragma unroll
    for (int j = 0; j < 32; j += 8)
        t[ty + j][tx] = in[(size_t)(by + ty + j) * Cn + bx + tx];
    __syncthreads();
    #pragma unroll
    for (int j = 0; j < 32; j += 8)
        out[(size_t)(bx + ty + j) * R + by + tx] = __float2half_rn(t[tx][ty + j]);
}

// ---------------------------------------------------------------------------
// fp16 GEMM: C[M,N] = A[M,K] @ Bt[N,K]^T + bias[N]   (R13 proven config)
// 128x128 CTA, BK=64, 256 thr (8 warps 2m x 4n, warp 64x32), 3-stage cp.async.
// ONE barrier per 64-K chunk; fragment loads via ldmatrix.x4.
// Stage: A 128x72 + B 128x72 halves; row stride 144 B (conflict-free).
// ---------------------------------------------------------------------------
template<typename OT>
__global__ __launch_bounds__(256) void gemm_h(
    const __half* __restrict__ A, const __half* __restrict__ Bt,
    const float* __restrict__ bias, OT* __restrict__ C,
    int M, int N, int K)
{
    extern __shared__ uint32_t smu[];
    const int STG = 9216;                 // u32 per stage (A 4608 + B 4608)
    const uint32_t sbase = smem_u32(smu);

    const int tid  = threadIdx.x;
    const int lane = tid & 31, warp = tid >> 5;
    const int wm = warp & 1;
    const int wn = warp >> 1;
    const int qp = lane & 3, qr = lane >> 2;
    const int brow = blockIdx.y * 128;
    const int bcol = blockIdx.x * 128;

    // ldmatrix lane-address components (row stride 144 B)
    const int lx15 = lane & 15;
    const int lhi  = lane >> 4;
    const int l8   = (lane >> 3) & 1;
    const int lx7  = lane & 7;
    const uint32_t aoff = (uint32_t)(wm * 64 + lx15) * 144 + lhi * 16;
    const uint32_t boff = 4608u * 4 + (uint32_t)(wn * 32 + lhi * 8 + lx7) * 144 + l8 * 16;

    float4 acc[4][4];
    #pragma unroll
    for (int i = 0; i < 4; ++i)
        #pragma unroll
        for (int j = 0; j < 4; ++j) acc[i][j] = make_float4(0.f, 0.f, 0.f, 0.f);

    const int NCH = K >> 6;               // 64-half K chunks

    auto load_stage = [&](int kt) {
        uint32_t base = sbase + (kt % 3) * STG * 4;
        #pragma unroll
        for (int i = 0; i < 4; ++i) {
            int idx = i * 256 + tid;       // 0..1023
            int row = idx >> 3;            // 0..127
            int c8  = idx & 7;             // 0..7 (8 halves each)
            uint32_t soff = (uint32_t)row * 144 + c8 * 16;
            cpa16(base + soff,
                  A + (size_t)(brow + row) * K + kt * 64 + c8 * 8);
            cpa16(base + 4608 * 4 + soff,
                  Bt + (size_t)(bcol + row) * K + kt * 64 + c8 * 8);
        }
        CPA_COMMIT();
    };

    load_stage(0);
    load_stage(1);

    for (int kt = 0; kt < NCH; ++kt) {
        if (kt + 1 < NCH) { CPA_WAIT(1); } else { CPA_WAIT(0); }
        __syncthreads();
        if (kt + 2 < NCH) load_stage(kt + 2);

        const uint32_t base = sbase + (kt % 3) * STG * 4;
        #pragma unroll
        for (int ks = 0; ks < 4; ++ks) {
            unsigned af[4][4];
            #pragma unroll
            for (int mt = 0; mt < 4; ++mt)
                ldmx4(af[mt][0], af[mt][1], af[mt][2], af[mt][3],
                      base + aoff + (uint32_t)mt * (16 * 144) + ks * 32);
            unsigned bf[4][2];
            #pragma unroll
            for (int ntp = 0; ntp < 2; ++ntp)
                ldmx4(bf[2*ntp][0], bf[2*ntp][1], bf[2*ntp+1][0], bf[2*ntp+1][1],
                      base + boff + (uint32_t)ntp * (16 * 144) + ks * 32);
            #pragma unroll
            for (int mt = 0; mt < 4; ++mt)
                #pragma unroll
                for (int nt = 0; nt < 4; ++nt)
                    mma16(acc[mt][nt], af[mt][0], af[mt][1], af[mt][2], af[mt][3],
                          bf[nt][0], bf[nt][1]);
        }
    }

    #pragma unroll
    for (int mt = 0; mt < 4; ++mt) {
        int r0 = brow + wm * 64 + mt * 16 + qr;
        #pragma unroll
        for (int nt = 0; nt < 4; ++nt) {
            int c = bcol + wn * 32 + nt * 8 + 2 * qp;
            float bx = bias[c], by = bias[c + 1];
            store2(C, (size_t)r0       * N + c, acc[mt][nt].x + bx, acc[mt][nt].y + by);
            store2(C, (size_t)(r0 + 8) * N + c, acc[mt][nt].z + bx, acc[mt][nt].w + by);
        }
    }
}

// ---------------------------------------------------------------------------
// Flash attention, fp16 m16n8k16, zero-shuffle P reuse, BASE-2 softmax.
// Q pre-scaled by 0.125*log2(e) in fp32; exp -> single ex2.approx.
// cp.async DOUBLE-BUFFERED K/V (one barrier/tile), ldmatrix for K and V frags.
// CTA: 64 q-rows (4 warps x 16), k-tiles of 64. qkv is HALF.
// ---------------------------------------------------------------------------
__global__ __launch_bounds__(128) void attn_h(
    const __half* __restrict__ qkv, __half* __restrict__ out)
{
    extern __shared__ __half smh[];
    const uint32_t sb = smem_u32(smh);
    const uint32_t KBUFB = 18432;      // bytes per (K+V) buffer
    const uint32_t VOFF  = 9216;       // V offset within buffer

    const int tid  = threadIdx.x;
    const int lane = tid & 31, w = tid >> 5;
    const int h = blockIdx.y, b = blockIdx.z;
    const int q0 = blockIdx.x * 64;
    const int qp = lane & 3;
    const int qr = lane >> 2;
    const unsigned FULL = 0xffffffffu;
    const float qscale = 0.125f * 1.44269504088896f;   // 1/sqrt(64) * log2(e)

    // ldmatrix lane components (row stride 144 B)
    const int lx7 = lane & 7;
    const int lhi = lane >> 4;
    const int l8  = (lane >> 3) & 1;
    const uint32_t kfoff = (uint32_t)(lhi * 8 + lx7) * 144 + l8 * 16;   // K frags (non-trans)
    const int lrow = lane & 15;                                          // V frags (trans)
    const int lcol = (lane >> 4) * 8;

    // ---- Q fragments (fp32 scale by qscale, then pack to half) ----
    unsigned qa[4][4];
    {
        const __half* Qg = qkv + (size_t)(b*TT + q0 + w*16) * (3*CC) + h*HD;
        #pragma unroll
        for (int ks = 0; ks < 4; ++ks) {
            int c0 = ks * 16 + 2 * qp;
            __half2 h00 = *(const __half2*)(Qg + (size_t)qr     * (3*CC) + c0);
            __half2 h10 = *(const __half2*)(Qg + (size_t)(qr+8) * (3*CC) + c0);
            __half2 h01 = *(const __half2*)(Qg + (size_t)qr     * (3*CC) + c0 + 8);
            __half2 h11 = *(const __half2*)(Qg + (size_t)(qr+8) * (3*CC) + c0 + 8);
            float2 f00 = __half22float2(h00), f10 = __half22float2(h10);
            float2 f01 = __half22float2(h01), f11 = __half22float2(h11);
            qa[ks][0] = packh2(f00.x * qscale, f00.y * qscale);
            qa[ks][1] = packh2(f10.x * qscale, f10.y * qscale);
            qa[ks][2] = packh2(f01.x * qscale, f01.y * qscale);
            qa[ks][3] = packh2(f11.x * qscale, f11.y * qscale);
        }
    }

    float4 o[8];
    #pragma unroll
    for (int i = 0; i < 8; ++i) o[i] = make_float4(0.f, 0.f, 0.f, 0.f);
    float m0 = -1e30f, m1 = -1e30f, l0 = 0.f, l1 = 0.f;

    const int nd = q0 >> 6;            // last key-tile index

    auto loadkv = [&](int kt, int buf) {
        const __half* kb = qkv + (size_t)(b*TT + kt*64) * (3*CC) + CC + h*HD;
        const __half* vb = kb + CC;
        const uint32_t kbuf = sb + buf * KBUFB;
        #pragma unroll
        for (int i = 0; i < 4; ++i) {
            int idx = i * 128 + tid;       // 0..511
            int key = idx >> 3;            // 0..63
            int d8  = (idx & 7) * 8;       // 0..56
            uint32_t off = (key * 72 + d8) * 2;
            const size_t g = (size_t)key * (3*CC) + d8;
            cpa16(kbuf + off,        kb + g);
            cpa16(kbuf + VOFF + off, vb + g);
        }
        CPA_COMMIT();
    };

    loadkv(0, 0);
    for (int kt = 0; kt <= nd; ++kt) {
        CPA_WAIT(0);
        __syncthreads();
        if (kt < nd) loadkv(kt + 1, (kt + 1) & 1);

        const uint32_t kbuf = sb + (kt & 1) * KBUFB;
        const uint32_t vbuf = kbuf + VOFF;

        // ---- S = Q @ K^T  (16 x 64, log2-domain scores) ----
        float4 s[8];
        #pragma unroll
        for (int nt = 0; nt < 8; ++nt) s[nt] = make_float4(0.f, 0.f, 0.f, 0.f);
        #pragma unroll
        for (int ks = 0; ks < 4; ++ks) {
            #pragma unroll
            for (int ntp = 0; ntp < 4; ++ntp) {
                unsigned b00, b01, b10, b11;
                ldmx4(b00, b01, b10, b11,
                      kbuf + kfoff + (uint32_t)ntp * (16 * 144) + ks * 32);
                mma16(s[2*ntp],     qa[ks][0], qa[ks][1], qa[ks][2], qa[ks][3], b00, b01);
                mma16(s[2*ntp + 1], qa[ks][0], qa[ks][1], qa[ks][2], qa[ks][3], b10, b11);
            }
        }

        // ---- causal mask (diagonal tile only) ----
        if (kt == nd) {
            const int rg0 = q0 + w * 16 + qr;
            const int rg1 = rg0 + 8;
            #pragma unroll
            for (int nt = 0; nt < 8; ++nt) {
                int cg = kt * 64 + nt * 8 + 2 * qp;
                if (cg     > rg0) s[nt].x = -1e30f;
                if (cg + 1 > rg0) s[nt].y = -1e30f;
                if (cg     > rg1) s[nt].z = -1e30f;
                if (cg + 1 > rg1) s[nt].w = -1e30f;
            }
        }

        // ---- online softmax (base 2) ----
        float mx0 = -1e30f, mx1 = -1e30f;
        #pragma unroll
        for (int nt = 0; nt < 8; ++nt) {
            mx0 = fmaxf(mx0, fmaxf(s[nt].x, s[nt].y));
            mx1 = fmaxf(mx1, fmaxf(s[nt].z, s[nt].w));
        }
        mx0 = fmaxf(mx0, __shfl_xor_sync(FULL, mx0, 1));
        mx0 = fmaxf(mx0, __shfl_xor_sync(FULL, mx0, 2));
        mx1 = fmaxf(mx1, __shfl_xor_sync(FULL, mx1, 1));
        mx1 = fmaxf(mx1, __shfl_xor_sync(FULL, mx1, 2));

        float nm0 = fmaxf(m0, mx0), nm1 = fmaxf(m1, mx1);
        float al0 = fexp2(m0 - nm0), al1 = fexp2(m1 - nm1);
        m0 = nm0; m1 = nm1;

        float sum0 = 0.f, sum1 = 0.f;
        #pragma unroll
        for (int nt = 0; nt < 8; ++nt) {
            s[nt].x = fexp2(s[nt].x - m0);
            s[nt].y = fexp2(s[nt].y - m0);
            s[nt].z = fexp2(s[nt].z - m1);
            s[nt].w = fexp2(s[nt].w - m1);
            sum0 += s[nt].x + s[nt].y;
            sum1 += s[nt].z + s[nt].w;
        }
        sum0 += __shfl_xor_sync(FULL, sum0, 1);
        sum0 += __shfl_xor_sync(FULL, sum0, 2);
        sum1 += __shfl_xor_sync(FULL, sum1, 1);
        sum1 += __shfl_xor_sync(FULL, sum1, 2);
        l0 = l0 * al0 + sum0;
        l1 = l1 * al1 + sum1;
        #pragma unroll
        for (int nt = 0; nt < 8; ++nt) {
            o[nt].x *= al0; o[nt].y *= al0; o[nt].z *= al1; o[nt].w *= al1;
        }

        // ---- O += P @ V : S packs into A-frags; V B-frags via ldmatrix.trans ----
        #pragma unroll
        for (int j = 0; j < 4; ++j) {
            unsigned a0 = packh2(s[2*j].x,     s[2*j].y);
            unsigned a1 = packh2(s[2*j].z,     s[2*j].w);
            unsigned a2 = packh2(s[2*j + 1].x, s[2*j + 1].y);
            unsigned a3 = packh2(s[2*j + 1].z, s[2*j + 1].w);
            const int kb = j * 16;            // key group
            const uint32_t rowaddr = vbuf + ((kb + lrow) * 72 + lcol) * 2;
            #pragma unroll
            for (int g2 = 0; g2 < 4; ++g2) {  // d-pair groups (nt = 2g2, 2g2+1)
                unsigned b00, b01, b10, b11;
                ldmx4t(b00, b01, b10, b11, rowaddr + g2 * 32);
                mma16(o[2*g2],     a0, a1, a2, a3, b00, b01);
                mma16(o[2*g2 + 1], a0, a1, a2, a3, b10, b11);
            }
        }
    }

    // ---- writeout to HALF [B*T, C] ----
    const float inv0 = 1.f / l0, inv1 = 1.f / l1;
    const int rg0 = b * TT + q0 + w * 16 + qr;
    __half* ob = out + (size_t)rg0 * CC + h * HD;
    #pragma unroll
    for (int nt = 0; nt < 8; ++nt) {
        int c = nt * 8 + 2 * qp;
        *(__half2*)(ob + c) =
            __float22half2_rn(make_float2(o[nt].x * inv0, o[nt].y * inv0));
        *(__half2*)(ob + (size_t)8 * CC + c) =
            __float22half2_rn(make_float2(o[nt].z * inv1, o[nt].w * inv1));
    }
}

// ---------------------------------------------------------------------------
extern "C" void kernel_launch(void* const* d_in, const int* in_sizes, int n_in,
                              void* d_out, int out_size)
{
    (void)in_sizes; (void)n_in; (void)out_size;
    const float* x     = (const float*)d_in[0];
    const float* w_qkv = (const float*)d_in[1];
    const float* b_qkv = (const float*)d_in[2];
    const float* w_out = (const float*)d_in[3];
    const float* b_out = (const float*)d_in[4];
    float* out = (float*)d_out;

    __half *qkvh, *atth, *xh, *wqkvT, *woutT;
    cudaGetSymbolAddress((void**)&qkvh,  g_qkvh);
    cudaGetSymbolAddress((void**)&atth,  g_atth);
    cudaGetSymbolAddress((void**)&xh,    g_xh);
    cudaGetSymbolAddress((void**)&wqkvT, g_wqkvT);
    cudaGetSymbolAddress((void**)&woutT, g_woutT);

    const int GEMM_SMEM = 3 * 9216 * 4;   // 110592 B
    const int ATTN_SMEM = 2 * 18432;      // 36864 B
    cudaFuncSetAttribute(gemm_h<__half>, cudaFuncAttributeMaxDynamicSharedMemorySize, GEMM_SMEM);
    cudaFuncSetAttribute(gemm_h<float>,  cudaFuncAttributeMaxDynamicSharedMemorySize, GEMM_SMEM);

    // 0) prepass: x -> half; weights -> transposed half [N][K]
    cvt_h<<<(MROWS * CC / 4 + 255) / 256, 256>>>(x, xh, MROWS * CC / 4);
    {
        dim3 blk(32, 8);
        transpose_h<<<dim3(3 * CC / 32, CC / 32), blk>>>(w_qkv, wqkvT, CC, 3 * CC);
        transpose_h<<<dim3(CC / 32, CC / 32), blk>>>(w_out, woutT, CC, CC);
    }

    // 1) qkv = x @ w_qkv + b_qkv   (M=4096, N=3072, K=1024) -> HALF
    {
        dim3 grid(3 * CC / 128, MROWS / 128);
        gemm_h<__half><<<grid, 256, GEMM_SMEM>>>(xh, wqkvT, b_qkv, qkvh, MROWS, 3 * CC, CC);
    }
    // 2) fused causal attention -> atth (half) [B*T, C]
    {
        dim3 grid(TT / 64, NH, BB);
        attn_h<<<grid, 128, ATTN_SMEM>>>(qkvh, atth);
    }
    // 3) out = att @ w_out + b_out (M=4096, N=1024, K=1024) -> fp32
    {
        dim3 grid(CC / 128, MROWS / 128);
        gemm_h<float><<<grid, 256, GEMM_SMEM>>>(atth, woutT, b_out, out, MROWS, CC, CC);
    }
}